// round 6
// baseline (speedup 1.0000x reference)
#include <cuda_runtime.h>
#include <math.h>

#define D_MODEL 768
#define SQ_LEN  2048
#define SKV_LEN 4096
#define NB      2
#define NH      12

// Scratch (allocation-free rule: __device__ globals)
__device__ float g_Q[NB * SQ_LEN * D_MODEL];    // 12.6 MB
__device__ float g_K[NB * SKV_LEN * D_MODEL];   // 25.2 MB
__device__ float g_V[NB * SKV_LEN * D_MODEL];   // 25.2 MB
__device__ float g_ctx[NB * SQ_LEN * D_MODEL];  // 12.6 MB

// ---------------------------------------------------------------------------
// SGEMM + bias: C[M,768] = A[M,768] @ W[768,768] + b[768]
// 128x128 block tile, BK=8, 256 threads, 8x8 per thread (split-half mapping).
// Double-buffered smem (ping-pong): ONE __syncthreads per k-slice.
// ---------------------------------------------------------------------------
__global__ __launch_bounds__(256)
void sgemm_bias(const float* __restrict__ A, const float* __restrict__ W,
                const float* __restrict__ bias, float* __restrict__ C) {
    __shared__ float Ats[2][8][132];   // [buf][k][row], transposed A tile
    __shared__ float Ws [2][8][132];   // [buf][k][col]

    const int tid = threadIdx.x;
    const int tx  = tid & 15;
    const int ty  = tid >> 4;
    const int bm  = blockIdx.x * 128;
    const int bn  = blockIdx.y * 128;

    // loaders
    const int arow = tid >> 1;          // 0..127
    const int acol = (tid & 1) << 2;    // 0 or 4
    const int wk   = tid >> 5;          // 0..7
    const int wn   = (tid & 31) << 2;   // 0..124

    const float* Ag = A + (size_t)(bm + arow) * D_MODEL + acol;
    const float* Wg = W + (size_t)wk * D_MODEL + bn + wn;

    float acc[8][8];
    #pragma unroll
    for (int i = 0; i < 8; i++)
        #pragma unroll
        for (int j = 0; j < 8; j++) acc[i][j] = 0.0f;

    // Preload tile 0 into buffer 0
    {
        float4 areg = *(const float4*)Ag;
        float4 wreg = *(const float4*)Wg;
        Ats[0][acol + 0][arow] = areg.x;
        Ats[0][acol + 1][arow] = areg.y;
        Ats[0][acol + 2][arow] = areg.z;
        Ats[0][acol + 3][arow] = areg.w;
        *(float4*)&Ws[0][wk][wn] = wreg;
    }
    __syncthreads();

    int buf = 0;
    for (int k0 = 8; k0 <= D_MODEL; k0 += 8) {
        float4 areg, wreg;
        const bool more = (k0 < D_MODEL);
        if (more) {
            areg = *(const float4*)(Ag + k0);
            wreg = *(const float4*)(Wg + (size_t)k0 * D_MODEL);
        }
        #pragma unroll
        for (int kk = 0; kk < 8; kk++) {
            float4 a0 = *(float4*)&Ats[buf][kk][ty * 4];
            float4 a1 = *(float4*)&Ats[buf][kk][64 + ty * 4];
            float4 b0 = *(float4*)&Ws[buf][kk][tx * 4];
            float4 b1 = *(float4*)&Ws[buf][kk][64 + tx * 4];
            float av[8] = {a0.x, a0.y, a0.z, a0.w, a1.x, a1.y, a1.z, a1.w};
            float bv[8] = {b0.x, b0.y, b0.z, b0.w, b1.x, b1.y, b1.z, b1.w};
            #pragma unroll
            for (int i = 0; i < 8; i++)
                #pragma unroll
                for (int j = 0; j < 8; j++)
                    acc[i][j] = fmaf(av[i], bv[j], acc[i][j]);
        }
        if (more) {
            const int nb = buf ^ 1;
            Ats[nb][acol + 0][arow] = areg.x;
            Ats[nb][acol + 1][arow] = areg.y;
            Ats[nb][acol + 2][arow] = areg.z;
            Ats[nb][acol + 3][arow] = areg.w;
            *(float4*)&Ws[nb][wk][wn] = wreg;
            __syncthreads();
            buf = nb;
        }
    }

    const float4 bv0 = *(const float4*)(bias + bn + tx * 4);
    const float4 bv1 = *(const float4*)(bias + bn + 64 + tx * 4);
    #pragma unroll
    for (int i = 0; i < 8; i++) {
        int row = bm + ((i < 4) ? (ty * 4 + i) : (64 + ty * 4 + (i - 4)));
        float4 o0 = make_float4(acc[i][0] + bv0.x, acc[i][1] + bv0.y,
                                acc[i][2] + bv0.z, acc[i][3] + bv0.w);
        float4 o1 = make_float4(acc[i][4] + bv1.x, acc[i][5] + bv1.y,
                                acc[i][6] + bv1.z, acc[i][7] + bv1.w);
        *(float4*)(C + (size_t)row * D_MODEL + bn + tx * 4) = o0;
        *(float4*)(C + (size_t)row * D_MODEL + bn + 64 + tx * 4) = o1;
    }
}

// ---------------------------------------------------------------------------
// Flash attention: per (b, h, q-tile of 64). BKV=64, DH=64.
// 256 threads (16x16), each computes a 4x4 S-tile and 4x4 O-tile.
// smem layouts are d-major (transposed) so both MMA phases read conflict-free
// float4s. Online softmax with shfl_xor reductions across the 16 tx lanes.
// ---------------------------------------------------------------------------
#define TS 68                       // padded row stride (floats), keeps float4 align
#define ATT_SMEM (4 * 64 * TS * 4)  // 69632 bytes

__global__ __launch_bounds__(256)
void attention_kernel(const float* __restrict__ Q, const float* __restrict__ K,
                      const float* __restrict__ V, float* __restrict__ O) {
    extern __shared__ float sm[];
    float* Qts = sm;                // [d=64][r=64] (+pad)
    float* Kts = sm + 64 * TS;      // [d=64][c=64]
    float* Vs  = sm + 2 * 64 * TS;  // [c=64][d=64]
    float* Pt  = sm + 3 * 64 * TS;  // [c=64][r=64]

    const int tid = threadIdx.x;
    const int tx  = tid & 15;
    const int ty  = tid >> 4;
    const int b   = blockIdx.z;
    const int h   = blockIdx.y;
    const int q0  = blockIdx.x * 64;

    const float* Qb = Q + ((size_t)b * SQ_LEN + q0) * D_MODEL + h * 64;
    const float* Kb = K + ((size_t)b * SKV_LEN) * D_MODEL + h * 64;
    const float* Vb = V + ((size_t)b * SKV_LEN) * D_MODEL + h * 64;

    // Load Q tile transposed, pre-scaled by 1/sqrt(64)
    #pragma unroll
    for (int it = 0; it < 4; it++) {
        int idx = tid + it * 256;       // float4 slot
        int r   = idx >> 4;             // 0..63
        int d4  = (idx & 15) << 2;      // 0..60
        float4 v = *(const float4*)(Qb + (size_t)r * D_MODEL + d4);
        Qts[(d4 + 0) * TS + r] = v.x * 0.125f;
        Qts[(d4 + 1) * TS + r] = v.y * 0.125f;
        Qts[(d4 + 2) * TS + r] = v.z * 0.125f;
        Qts[(d4 + 3) * TS + r] = v.w * 0.125f;
    }

    float m_i[4], l_i[4], o_acc[4][4];
    #pragma unroll
    for (int i = 0; i < 4; i++) {
        m_i[i] = -1e30f;
        l_i[i] = 0.0f;
        #pragma unroll
        for (int j = 0; j < 4; j++) o_acc[i][j] = 0.0f;
    }

    for (int kv0 = 0; kv0 < SKV_LEN; kv0 += 64) {
        __syncthreads();    // prev iter's PV (reads Vs, Pt) done; Q writes done
        #pragma unroll
        for (int it = 0; it < 4; it++) {
            int idx = tid + it * 256;
            int r   = idx >> 4;
            int d4  = (idx & 15) << 2;
            float4 kv = *(const float4*)(Kb + (size_t)(kv0 + r) * D_MODEL + d4);
            Kts[(d4 + 0) * TS + r] = kv.x;
            Kts[(d4 + 1) * TS + r] = kv.y;
            Kts[(d4 + 2) * TS + r] = kv.z;
            Kts[(d4 + 3) * TS + r] = kv.w;
            float4 vv = *(const float4*)(Vb + (size_t)(kv0 + r) * D_MODEL + d4);
            *(float4*)&Vs[r * TS + d4] = vv;
        }
        __syncthreads();

        // S = (Q*scale) @ K^T  (64x64, 4x4 per thread)
        float s[4][4];
        #pragma unroll
        for (int i = 0; i < 4; i++)
            #pragma unroll
            for (int j = 0; j < 4; j++) s[i][j] = 0.0f;

        #pragma unroll 8
        for (int d = 0; d < 64; d++) {
            float4 a  = *(float4*)&Qts[d * TS + ty * 4];
            float4 bb = *(float4*)&Kts[d * TS + tx * 4];
            float av[4] = {a.x, a.y, a.z, a.w};
            float bv[4] = {bb.x, bb.y, bb.z, bb.w};
            #pragma unroll
            for (int i = 0; i < 4; i++)
                #pragma unroll
                for (int j = 0; j < 4; j++)
                    s[i][j] = fmaf(av[i], bv[j], s[i][j]);
        }

        // Online softmax (row stats across the 16 tx lanes of each half-warp)
        #pragma unroll
        for (int i = 0; i < 4; i++) {
            float mt = fmaxf(fmaxf(s[i][0], s[i][1]), fmaxf(s[i][2], s[i][3]));
            #pragma unroll
            for (int o = 8; o > 0; o >>= 1)
                mt = fmaxf(mt, __shfl_xor_sync(0xffffffffu, mt, o));
            float mn   = fmaxf(m_i[i], mt);
            float corr = __expf(m_i[i] - mn);
            m_i[i] = mn;
            float rs = 0.0f;
            #pragma unroll
            for (int j = 0; j < 4; j++) {
                s[i][j] = __expf(s[i][j] - mn);
                rs += s[i][j];
            }
            #pragma unroll
            for (int o = 8; o > 0; o >>= 1)
                rs += __shfl_xor_sync(0xffffffffu, rs, o);
            l_i[i] = l_i[i] * corr + rs;
            #pragma unroll
            for (int j = 0; j < 4; j++) o_acc[i][j] *= corr;
        }

        // Stage P transposed: Pt[c][r]
        #pragma unroll
        for (int j = 0; j < 4; j++) {
            float4 pv = make_float4(s[0][j], s[1][j], s[2][j], s[3][j]);
            *(float4*)&Pt[(tx * 4 + j) * TS + ty * 4] = pv;
        }
        __syncthreads();

        // O += P @ V  (dot over c)
        #pragma unroll 8
        for (int c = 0; c < 64; c++) {
            float4 a  = *(float4*)&Pt[c * TS + ty * 4];
            float4 bb = *(float4*)&Vs[c * TS + tx * 4];
            float av[4] = {a.x, a.y, a.z, a.w};
            float bv[4] = {bb.x, bb.y, bb.z, bb.w};
            #pragma unroll
            for (int i = 0; i < 4; i++)
                #pragma unroll
                for (int j = 0; j < 4; j++)
                    o_acc[i][j] = fmaf(av[i], bv[j], o_acc[i][j]);
        }
    }

    float* Ob = O + ((size_t)b * SQ_LEN + q0) * D_MODEL + h * 64;
    #pragma unroll
    for (int i = 0; i < 4; i++) {
        float inv = 1.0f / l_i[i];
        float4 ov = make_float4(o_acc[i][0] * inv, o_acc[i][1] * inv,
                                o_acc[i][2] * inv, o_acc[i][3] * inv);
        *(float4*)(Ob + (size_t)(ty * 4 + i) * D_MODEL + tx * 4) = ov;
    }
}

// ---------------------------------------------------------------------------
extern "C" void kernel_launch(void* const* d_in, const int* in_sizes, int n_in,
                              void* d_out, int out_size) {
    const float* hs  = (const float*)d_in[0];
    const float* enc = (const float*)d_in[1];
    const float* Wq  = (const float*)d_in[2];
    const float* bq  = (const float*)d_in[3];
    const float* Wk  = (const float*)d_in[4];
    const float* bk  = (const float*)d_in[5];
    const float* Wv  = (const float*)d_in[6];
    const float* bv  = (const float*)d_in[7];
    const float* Wo  = (const float*)d_in[8];
    const float* bo  = (const float*)d_in[9];
    float* out = (float*)d_out;

    float *Qp, *Kp, *Vp, *Cp;
    cudaGetSymbolAddress((void**)&Qp, g_Q);
    cudaGetSymbolAddress((void**)&Kp, g_K);
    cudaGetSymbolAddress((void**)&Vp, g_V);
    cudaGetSymbolAddress((void**)&Cp, g_ctx);

    cudaFuncSetAttribute(attention_kernel,
                         cudaFuncAttributeMaxDynamicSharedMemorySize, ATT_SMEM);

    const int MQ  = NB * SQ_LEN;    // 4096
    const int MKV = NB * SKV_LEN;   // 8192

    sgemm_bias<<<dim3(MQ / 128, D_MODEL / 128), 256>>>(hs, Wq, bq, Qp);
    sgemm_bias<<<dim3(MKV / 128, D_MODEL / 128), 256>>>(enc, Wk, bk, Kp);
    sgemm_bias<<<dim3(MKV / 128, D_MODEL / 128), 256>>>(enc, Wv, bv, Vp);

    attention_kernel<<<dim3(SQ_LEN / 64, NH, NB), 256, ATT_SMEM>>>(Qp, Kp, Vp, Cp);

    sgemm_bias<<<dim3(MQ / 128, D_MODEL / 128), 256>>>(Cp, Wo, bo, out);
}

// round 7
// speedup vs baseline: 2.0643x; 2.0643x over previous
#include <cuda_runtime.h>
#include <math.h>
#include <stdint.h>

#define D_MODEL 768
#define SQ_LEN  2048
#define SKV_LEN 4096
#define NB      2
#define NH      12

// Scratch (allocation-free rule: __device__ globals)
__device__ float g_Q[NB * SQ_LEN * D_MODEL];    // 12.6 MB
__device__ float g_K[NB * SKV_LEN * D_MODEL];   // 25.2 MB
__device__ float g_V[NB * SKV_LEN * D_MODEL];   // 25.2 MB
__device__ float g_ctx[NB * SQ_LEN * D_MODEL];  // 12.6 MB

// ---------------------------------------------------------------------------
// SGEMM + bias: C[M,768] = A[M,768] @ W[768,768] + b[768]
// 128x128 tile, BK=8, 256 threads, 8x8/thread, double-buffered smem.
// ---------------------------------------------------------------------------
__global__ __launch_bounds__(256)
void sgemm_bias(const float* __restrict__ A, const float* __restrict__ W,
                const float* __restrict__ bias, float* __restrict__ C) {
    __shared__ float Ats[2][8][132];
    __shared__ float Ws [2][8][132];

    const int tid = threadIdx.x;
    const int tx  = tid & 15;
    const int ty  = tid >> 4;
    const int bm  = blockIdx.x * 128;
    const int bn  = blockIdx.y * 128;

    const int arow = tid >> 1;
    const int acol = (tid & 1) << 2;
    const int wk   = tid >> 5;
    const int wn   = (tid & 31) << 2;

    const float* Ag = A + (size_t)(bm + arow) * D_MODEL + acol;
    const float* Wg = W + (size_t)wk * D_MODEL + bn + wn;

    float acc[8][8];
    #pragma unroll
    for (int i = 0; i < 8; i++)
        #pragma unroll
        for (int j = 0; j < 8; j++) acc[i][j] = 0.0f;

    {
        float4 areg = *(const float4*)Ag;
        float4 wreg = *(const float4*)Wg;
        Ats[0][acol + 0][arow] = areg.x;
        Ats[0][acol + 1][arow] = areg.y;
        Ats[0][acol + 2][arow] = areg.z;
        Ats[0][acol + 3][arow] = areg.w;
        *(float4*)&Ws[0][wk][wn] = wreg;
    }
    __syncthreads();

    int buf = 0;
    for (int k0 = 8; k0 <= D_MODEL; k0 += 8) {
        float4 areg, wreg;
        const bool more = (k0 < D_MODEL);
        if (more) {
            areg = *(const float4*)(Ag + k0);
            wreg = *(const float4*)(Wg + (size_t)k0 * D_MODEL);
        }
        #pragma unroll
        for (int kk = 0; kk < 8; kk++) {
            float4 a0 = *(float4*)&Ats[buf][kk][ty * 4];
            float4 a1 = *(float4*)&Ats[buf][kk][64 + ty * 4];
            float4 b0 = *(float4*)&Ws[buf][kk][tx * 4];
            float4 b1 = *(float4*)&Ws[buf][kk][64 + tx * 4];
            float av[8] = {a0.x, a0.y, a0.z, a0.w, a1.x, a1.y, a1.z, a1.w};
            float bv[8] = {b0.x, b0.y, b0.z, b0.w, b1.x, b1.y, b1.z, b1.w};
            #pragma unroll
            for (int i = 0; i < 8; i++)
                #pragma unroll
                for (int j = 0; j < 8; j++)
                    acc[i][j] = fmaf(av[i], bv[j], acc[i][j]);
        }
        if (more) {
            const int nb = buf ^ 1;
            Ats[nb][acol + 0][arow] = areg.x;
            Ats[nb][acol + 1][arow] = areg.y;
            Ats[nb][acol + 2][arow] = areg.z;
            Ats[nb][acol + 3][arow] = areg.w;
            *(float4*)&Ws[nb][wk][wn] = wreg;
            __syncthreads();
            buf = nb;
        }
    }

    const float4 bv0 = *(const float4*)(bias + bn + tx * 4);
    const float4 bv1 = *(const float4*)(bias + bn + 64 + tx * 4);
    #pragma unroll
    for (int i = 0; i < 8; i++) {
        int row = bm + ((i < 4) ? (ty * 4 + i) : (64 + ty * 4 + (i - 4)));
        float4 o0 = make_float4(acc[i][0] + bv0.x, acc[i][1] + bv0.y,
                                acc[i][2] + bv0.z, acc[i][3] + bv0.w);
        float4 o1 = make_float4(acc[i][4] + bv1.x, acc[i][5] + bv1.y,
                                acc[i][6] + bv1.z, acc[i][7] + bv1.w);
        *(float4*)(C + (size_t)row * D_MODEL + bn + tx * 4) = o0;
        *(float4*)(C + (size_t)row * D_MODEL + bn + 64 + tx * 4) = o1;
    }
}

// ---------------------------------------------------------------------------
// tf32 mma.sync helpers
// ---------------------------------------------------------------------------
__device__ __forceinline__ uint32_t f2tf32(float x) {
    uint32_t r;
    asm("cvt.rna.tf32.f32 %0, %1;" : "=r"(r) : "f"(x));
    return r;
}

__device__ __forceinline__ void mma_tf32(float* c, const uint32_t* a,
                                         uint32_t b0, uint32_t b1) {
    asm volatile(
        "mma.sync.aligned.m16n8k8.row.col.f32.tf32.tf32.f32 "
        "{%0,%1,%2,%3}, {%4,%5,%6,%7}, {%8,%9}, {%0,%1,%2,%3};\n"
        : "+f"(c[0]), "+f"(c[1]), "+f"(c[2]), "+f"(c[3])
        : "r"(a[0]), "r"(a[1]), "r"(a[2]), "r"(a[3]), "r"(b0), "r"(b1));
}

// ---------------------------------------------------------------------------
// Flash attention, tf32 tensor-core version.
// Per CTA: (b, h, 64 q-rows). 4 warps x 16 q-rows. BKV=64, DH=64.
// Q lives in registers as tf32 A-fragments. K/V row-major in smem (stride 68,
// conflict-free B-fragment loads). P stays in registers: S-accumulator is fed
// straight back as the PV A-fragment with V rows permuted k -> 2(k%4)+(k/4).
// ---------------------------------------------------------------------------
#define KVS 68   // smem row stride (floats) for K and V tiles

__global__ void __launch_bounds__(128, 3)
attention_mma(const float* __restrict__ Q, const float* __restrict__ K,
              const float* __restrict__ V, float* __restrict__ O) {
    __shared__ uint32_t Ks[64 * KVS];
    __shared__ uint32_t Vs[64 * KVS];

    const int tid  = threadIdx.x;
    const int w    = tid >> 5;          // warp 0..3
    const int lane = tid & 31;
    const int g    = lane >> 2;         // groupID 0..7
    const int tig  = lane & 3;          // thread-in-group 0..3
    const int b    = blockIdx.z;
    const int h    = blockIdx.y;
    const int q0   = blockIdx.x * 64;

    // --- Q fragments (16 rows per warp), scaled by 1/sqrt(64), tf32 ---
    uint32_t qf[8][4];
    {
        const float* Qb = Q + ((size_t)(b * SQ_LEN + q0 + w * 16)) * D_MODEL + h * 64;
        #pragma unroll
        for (int kt = 0; kt < 8; kt++) {
            int d0 = kt * 8 + tig;
            qf[kt][0] = f2tf32(Qb[(size_t)g       * D_MODEL + d0]     * 0.125f);
            qf[kt][1] = f2tf32(Qb[(size_t)(g + 8) * D_MODEL + d0]     * 0.125f);
            qf[kt][2] = f2tf32(Qb[(size_t)g       * D_MODEL + d0 + 4] * 0.125f);
            qf[kt][3] = f2tf32(Qb[(size_t)(g + 8) * D_MODEL + d0 + 4] * 0.125f);
        }
    }

    float oacc[8][4];
    #pragma unroll
    for (int nt = 0; nt < 8; nt++)
        #pragma unroll
        for (int j = 0; j < 4; j++) oacc[nt][j] = 0.0f;

    float m_lo = -1e30f, m_hi = -1e30f, l_lo = 0.0f, l_hi = 0.0f;

    const float* Kb0 = K + ((size_t)b * SKV_LEN) * D_MODEL + h * 64;
    const float* Vb0 = V + ((size_t)b * SKV_LEN) * D_MODEL + h * 64;

    for (int kv0 = 0; kv0 < SKV_LEN; kv0 += 64) {
        __syncthreads();    // previous iteration's B-loads done
        // --- load K,V tile (64x64 each), convert to tf32, row-major ---
        #pragma unroll
        for (int it = 0; it < 8; it++) {
            int idx = tid + it * 128;       // float4 slot
            int r   = idx >> 4;             // 0..63
            int d4  = (idx & 15) << 2;      // 0..60
            float4 kx = *(const float4*)(Kb0 + (size_t)(kv0 + r) * D_MODEL + d4);
            uint4 kq = make_uint4(f2tf32(kx.x), f2tf32(kx.y), f2tf32(kx.z), f2tf32(kx.w));
            *(uint4*)&Ks[r * KVS + d4] = kq;
            float4 vx = *(const float4*)(Vb0 + (size_t)(kv0 + r) * D_MODEL + d4);
            uint4 vq = make_uint4(f2tf32(vx.x), f2tf32(vx.y), f2tf32(vx.z), f2tf32(vx.w));
            *(uint4*)&Vs[r * KVS + d4] = vq;
        }
        __syncthreads();

        // --- S = Q @ K^T  (16x64 per warp) ---
        float sacc[8][4];
        #pragma unroll
        for (int nt = 0; nt < 8; nt++)
            #pragma unroll
            for (int j = 0; j < 4; j++) sacc[nt][j] = 0.0f;

        #pragma unroll
        for (int kt = 0; kt < 8; kt++) {
            int dcol = kt * 8 + tig;
            #pragma unroll
            for (int nt = 0; nt < 8; nt++) {
                uint32_t b0 = Ks[(nt * 8 + g) * KVS + dcol];
                uint32_t b1 = Ks[(nt * 8 + g) * KVS + dcol + 4];
                mma_tf32(sacc[nt], qf[kt], b0, b1);
            }
        }

        // --- online softmax (rows g and g+8; reduce across the 4 tig lanes) ---
        float mt_lo = -1e30f, mt_hi = -1e30f;
        #pragma unroll
        for (int nt = 0; nt < 8; nt++) {
            mt_lo = fmaxf(mt_lo, fmaxf(sacc[nt][0], sacc[nt][1]));
            mt_hi = fmaxf(mt_hi, fmaxf(sacc[nt][2], sacc[nt][3]));
        }
        mt_lo = fmaxf(mt_lo, __shfl_xor_sync(0xffffffffu, mt_lo, 1));
        mt_lo = fmaxf(mt_lo, __shfl_xor_sync(0xffffffffu, mt_lo, 2));
        mt_hi = fmaxf(mt_hi, __shfl_xor_sync(0xffffffffu, mt_hi, 1));
        mt_hi = fmaxf(mt_hi, __shfl_xor_sync(0xffffffffu, mt_hi, 2));

        float mn_lo = fmaxf(m_lo, mt_lo);
        float mn_hi = fmaxf(m_hi, mt_hi);
        float corr_lo = __expf(m_lo - mn_lo);
        float corr_hi = __expf(m_hi - mn_hi);
        m_lo = mn_lo;
        m_hi = mn_hi;

        float rs_lo = 0.0f, rs_hi = 0.0f;
        uint32_t pf[8][4];          // P as A-fragments (acc->A relabeling)
        #pragma unroll
        for (int nt = 0; nt < 8; nt++) {
            float p0 = __expf(sacc[nt][0] - m_lo);  // (g,   2tig)
            float p1 = __expf(sacc[nt][1] - m_lo);  // (g,   2tig+1)
            float p2 = __expf(sacc[nt][2] - m_hi);  // (g+8, 2tig)
            float p3 = __expf(sacc[nt][3] - m_hi);  // (g+8, 2tig+1)
            rs_lo += p0 + p1;
            rs_hi += p2 + p3;
            pf[nt][0] = f2tf32(p0);     // a0: (g,   k=tig   -> kv 2tig)
            pf[nt][1] = f2tf32(p2);     // a1: (g+8, k=tig   -> kv 2tig)
            pf[nt][2] = f2tf32(p1);     // a2: (g,   k=tig+4 -> kv 2tig+1)
            pf[nt][3] = f2tf32(p3);     // a3: (g+8, k=tig+4 -> kv 2tig+1)
        }
        rs_lo += __shfl_xor_sync(0xffffffffu, rs_lo, 1);
        rs_lo += __shfl_xor_sync(0xffffffffu, rs_lo, 2);
        rs_hi += __shfl_xor_sync(0xffffffffu, rs_hi, 1);
        rs_hi += __shfl_xor_sync(0xffffffffu, rs_hi, 2);
        l_lo = l_lo * corr_lo + rs_lo;
        l_hi = l_hi * corr_hi + rs_hi;

        #pragma unroll
        for (int nt = 0; nt < 8; nt++) {
            oacc[nt][0] *= corr_lo;
            oacc[nt][1] *= corr_lo;
            oacc[nt][2] *= corr_hi;
            oacc[nt][3] *= corr_hi;
        }

        // --- O += P @ V  (V rows permuted to match A-fragment k order) ---
        #pragma unroll
        for (int kt = 0; kt < 8; kt++) {
            int r0 = kt * 8 + 2 * tig;
            #pragma unroll
            for (int nt = 0; nt < 8; nt++) {
                uint32_t b0 = Vs[r0 * KVS + nt * 8 + g];
                uint32_t b1 = Vs[(r0 + 1) * KVS + nt * 8 + g];
                mma_tf32(oacc[nt], pf[kt], b0, b1);
            }
        }
    }

    // --- finalize ---
    float inv_lo = 1.0f / l_lo;
    float inv_hi = 1.0f / l_hi;
    float* Ob = O + ((size_t)(b * SQ_LEN + q0 + w * 16)) * D_MODEL + h * 64;
    #pragma unroll
    for (int nt = 0; nt < 8; nt++) {
        int col = nt * 8 + 2 * tig;
        float2 v0 = make_float2(oacc[nt][0] * inv_lo, oacc[nt][1] * inv_lo);
        float2 v1 = make_float2(oacc[nt][2] * inv_hi, oacc[nt][3] * inv_hi);
        *(float2*)(Ob + (size_t)g       * D_MODEL + col) = v0;
        *(float2*)(Ob + (size_t)(g + 8) * D_MODEL + col) = v1;
    }
}

// ---------------------------------------------------------------------------
extern "C" void kernel_launch(void* const* d_in, const int* in_sizes, int n_in,
                              void* d_out, int out_size) {
    const float* hs  = (const float*)d_in[0];
    const float* enc = (const float*)d_in[1];
    const float* Wq  = (const float*)d_in[2];
    const float* bq  = (const float*)d_in[3];
    const float* Wk  = (const float*)d_in[4];
    const float* bk  = (const float*)d_in[5];
    const float* Wv  = (const float*)d_in[6];
    const float* bv  = (const float*)d_in[7];
    const float* Wo  = (const float*)d_in[8];
    const float* bo  = (const float*)d_in[9];
    float* out = (float*)d_out;

    float *Qp, *Kp, *Vp, *Cp;
    cudaGetSymbolAddress((void**)&Qp, g_Q);
    cudaGetSymbolAddress((void**)&Kp, g_K);
    cudaGetSymbolAddress((void**)&Vp, g_V);
    cudaGetSymbolAddress((void**)&Cp, g_ctx);

    const int MQ  = NB * SQ_LEN;    // 4096
    const int MKV = NB * SKV_LEN;   // 8192

    sgemm_bias<<<dim3(MQ / 128, D_MODEL / 128), 256>>>(hs, Wq, bq, Qp);
    sgemm_bias<<<dim3(MKV / 128, D_MODEL / 128), 256>>>(enc, Wk, bk, Kp);
    sgemm_bias<<<dim3(MKV / 128, D_MODEL / 128), 256>>>(enc, Wv, bv, Vp);

    attention_mma<<<dim3(SQ_LEN / 64, NH, NB), 128>>>(Qp, Kp, Vp, Cp);

    sgemm_bias<<<dim3(MQ / 128, D_MODEL / 128), 256>>>(Cp, Wo, bo, out);
}

// round 16
// speedup vs baseline: 2.3528x; 1.1397x over previous
#include <cuda_runtime.h>
#include <math.h>
#include <stdint.h>

#define D_MODEL 768
#define SQ_LEN  2048
#define SKV_LEN 4096
#define NB      2
#define NH      12

// Scratch (allocation-free rule: __device__ globals)
__device__ float g_Q[NB * SQ_LEN * D_MODEL];    // 12.6 MB
__device__ float g_K[NB * SKV_LEN * D_MODEL];   // 25.2 MB
__device__ float g_V[NB * SKV_LEN * D_MODEL];   // 25.2 MB
__device__ float g_ctx[NB * SQ_LEN * D_MODEL];  // 12.6 MB

// ---------------------------------------------------------------------------
// tf32 mma.sync helpers
// ---------------------------------------------------------------------------
__device__ __forceinline__ uint32_t f2tf32(float x) {
    uint32_t r;
    asm("cvt.rna.tf32.f32 %0, %1;" : "=r"(r) : "f"(x));
    return r;
}

__device__ __forceinline__ void split_tf32(float x, uint32_t& hi, uint32_t& lo) {
    hi = f2tf32(x);
    lo = f2tf32(x - __uint_as_float(hi));
}

__device__ __forceinline__ void mma_tf32(float* c, const uint32_t* a,
                                         uint32_t b0, uint32_t b1) {
    asm volatile(
        "mma.sync.aligned.m16n8k8.row.col.f32.tf32.tf32.f32 "
        "{%0,%1,%2,%3}, {%4,%5,%6,%7}, {%8,%9}, {%0,%1,%2,%3};\n"
        : "+f"(c[0]), "+f"(c[1]), "+f"(c[2]), "+f"(c[3])
        : "r"(a[0]), "r"(a[1]), "r"(a[2]), "r"(a[3]), "r"(b0), "r"(b1));
}

// ---------------------------------------------------------------------------
// 3xTF32 tensor-core GEMM + bias: C[M,768] = A[M,768] @ W[768,768] + b
// CTA: 128m x 64n, 128 threads (4 warps x 32m x 64n). BK=16, double-buffered.
// Each operand is split x = hi + lo (tf32 pair); C = ah*bh + al*bh + ah*bl
// -> fp32-level accuracy on the tensor pipe.
// A smem [m][k] stride 20 (frag bank = 20g+tig : permutation, conflict-free)
// W smem [k][n] stride 72 (frag bank = 8tig+g   : permutation, conflict-free)
// ---------------------------------------------------------------------------
#define GBK 16

__global__ void __launch_bounds__(128)
gemm3xtf32_bias(const float* __restrict__ A, const float* __restrict__ W,
                const float* __restrict__ bias, float* __restrict__ C) {
    __shared__ float As[2][128 * 20];
    __shared__ float Bs[2][GBK * 72];

    const int tid  = threadIdx.x;
    const int w    = tid >> 5;
    const int lane = tid & 31;
    const int g    = lane >> 2;
    const int tig  = lane & 3;
    const int bm   = blockIdx.x * 128;
    const int bn   = blockIdx.y * 64;

    float acc[2][8][4];
    #pragma unroll
    for (int mt = 0; mt < 2; mt++)
        #pragma unroll
        for (int nt = 0; nt < 8; nt++)
            #pragma unroll
            for (int j = 0; j < 4; j++) acc[mt][nt][j] = 0.0f;

    // ---- loaders: A 512 float4 slots (4/thread), W 256 slots (2/thread) ----
    {   // preload k0 = 0 into buffer 0
        #pragma unroll
        for (int i = 0; i < 4; i++) {
            int s = tid + i * 128, m = s >> 2, c = s & 3;
            float4 v = *(const float4*)(A + (size_t)(bm + m) * D_MODEL + c * 4);
            *(float4*)&As[0][m * 20 + c * 4] = v;
        }
        #pragma unroll
        for (int i = 0; i < 2; i++) {
            int s = tid + i * 128, k = s >> 4, c = s & 15;
            float4 v = *(const float4*)(W + (size_t)k * D_MODEL + bn + c * 4);
            *(float4*)&Bs[0][k * 72 + c * 4] = v;
        }
    }
    __syncthreads();

    int buf = 0;
    for (int k0 = 0; k0 < D_MODEL; k0 += GBK) {
        const bool more = (k0 + GBK) < D_MODEL;
        float4 apre[4], wpre[2];
        if (more) {
            #pragma unroll
            for (int i = 0; i < 4; i++) {
                int s = tid + i * 128, m = s >> 2, c = s & 3;
                apre[i] = *(const float4*)(A + (size_t)(bm + m) * D_MODEL + k0 + GBK + c * 4);
            }
            #pragma unroll
            for (int i = 0; i < 2; i++) {
                int s = tid + i * 128, k = s >> 4, c = s & 15;
                wpre[i] = *(const float4*)(W + (size_t)(k0 + GBK + k) * D_MODEL + bn + c * 4);
            }
        }

        #pragma unroll
        for (int kt = 0; kt < 2; kt++) {
            const int kk = kt * 8;
            uint32_t ah[2][4], al[2][4];
            #pragma unroll
            for (int mt = 0; mt < 2; mt++) {
                const float* Ab = &As[buf][(w * 32 + mt * 16) * 20 + kk];
                split_tf32(Ab[g * 20 + tig],           ah[mt][0], al[mt][0]);
                split_tf32(Ab[(g + 8) * 20 + tig],     ah[mt][1], al[mt][1]);
                split_tf32(Ab[g * 20 + tig + 4],       ah[mt][2], al[mt][2]);
                split_tf32(Ab[(g + 8) * 20 + tig + 4], ah[mt][3], al[mt][3]);
            }
            #pragma unroll
            for (int nt = 0; nt < 8; nt++) {
                uint32_t bh0, bl0, bh1, bl1;
                split_tf32(Bs[buf][(kk + tig) * 72 + nt * 8 + g],     bh0, bl0);
                split_tf32(Bs[buf][(kk + tig + 4) * 72 + nt * 8 + g], bh1, bl1);
                #pragma unroll
                for (int mt = 0; mt < 2; mt++) {
                    mma_tf32(acc[mt][nt], ah[mt], bh0, bh1);
                    mma_tf32(acc[mt][nt], al[mt], bh0, bh1);
                    mma_tf32(acc[mt][nt], ah[mt], bl0, bl1);
                }
            }
        }

        if (more) {
            const int nb = buf ^ 1;
            __syncthreads();
            #pragma unroll
            for (int i = 0; i < 4; i++) {
                int s = tid + i * 128, m = s >> 2, c = s & 3;
                *(float4*)&As[nb][m * 20 + c * 4] = apre[i];
            }
            #pragma unroll
            for (int i = 0; i < 2; i++) {
                int s = tid + i * 128, k = s >> 4, c = s & 15;
                *(float4*)&Bs[nb][k * 72 + c * 4] = wpre[i];
            }
            __syncthreads();
            buf = nb;
        }
    }

    // ---- epilogue: bias + store ----
    #pragma unroll
    for (int mt = 0; mt < 2; mt++) {
        int row0 = bm + w * 32 + mt * 16 + g;
        #pragma unroll
        for (int nt = 0; nt < 8; nt++) {
            int col = bn + nt * 8 + 2 * tig;
            float2 bv = *(const float2*)(bias + col);
            float2 v0 = make_float2(acc[mt][nt][0] + bv.x, acc[mt][nt][1] + bv.y);
            float2 v1 = make_float2(acc[mt][nt][2] + bv.x, acc[mt][nt][3] + bv.y);
            *(float2*)(C + (size_t)row0 * D_MODEL + col) = v0;
            *(float2*)(C + (size_t)(row0 + 8) * D_MODEL + col) = v1;
        }
    }
}

// ---------------------------------------------------------------------------
// Flash attention, tf32 tensor-core version (unchanged from R7, measured
// 458.6us at occ 15.9% / tensor 37.2%).
// ---------------------------------------------------------------------------
#define KVS 68

__global__ void __launch_bounds__(128, 3)
attention_mma(const float* __restrict__ Q, const float* __restrict__ K,
              const float* __restrict__ V, float* __restrict__ O) {
    __shared__ uint32_t Ks[64 * KVS];
    __shared__ uint32_t Vs[64 * KVS];

    const int tid  = threadIdx.x;
    const int w    = tid >> 5;
    const int lane = tid & 31;
    const int g    = lane >> 2;
    const int tig  = lane & 3;
    const int b    = blockIdx.z;
    const int h    = blockIdx.y;
    const int q0   = blockIdx.x * 64;

    uint32_t qf[8][4];
    {
        const float* Qb = Q + ((size_t)(b * SQ_LEN + q0 + w * 16)) * D_MODEL + h * 64;
        #pragma unroll
        for (int kt = 0; kt < 8; kt++) {
            int d0 = kt * 8 + tig;
            qf[kt][0] = f2tf32(Qb[(size_t)g       * D_MODEL + d0]     * 0.125f);
            qf[kt][1] = f2tf32(Qb[(size_t)(g + 8) * D_MODEL + d0]     * 0.125f);
            qf[kt][2] = f2tf32(Qb[(size_t)g       * D_MODEL + d0 + 4] * 0.125f);
            qf[kt][3] = f2tf32(Qb[(size_t)(g + 8) * D_MODEL + d0 + 4] * 0.125f);
        }
    }

    float oacc[8][4];
    #pragma unroll
    for (int nt = 0; nt < 8; nt++)
        #pragma unroll
        for (int j = 0; j < 4; j++) oacc[nt][j] = 0.0f;

    float m_lo = -1e30f, m_hi = -1e30f, l_lo = 0.0f, l_hi = 0.0f;

    const float* Kb0 = K + ((size_t)b * SKV_LEN) * D_MODEL + h * 64;
    const float* Vb0 = V + ((size_t)b * SKV_LEN) * D_MODEL + h * 64;

    for (int kv0 = 0; kv0 < SKV_LEN; kv0 += 64) {
        __syncthreads();
        #pragma unroll
        for (int it = 0; it < 8; it++) {
            int idx = tid + it * 128;
            int r   = idx >> 4;
            int d4  = (idx & 15) << 2;
            float4 kx = *(const float4*)(Kb0 + (size_t)(kv0 + r) * D_MODEL + d4);
            uint4 kq = make_uint4(f2tf32(kx.x), f2tf32(kx.y), f2tf32(kx.z), f2tf32(kx.w));
            *(uint4*)&Ks[r * KVS + d4] = kq;
            float4 vx = *(const float4*)(Vb0 + (size_t)(kv0 + r) * D_MODEL + d4);
            uint4 vq = make_uint4(f2tf32(vx.x), f2tf32(vx.y), f2tf32(vx.z), f2tf32(vx.w));
            *(uint4*)&Vs[r * KVS + d4] = vq;
        }
        __syncthreads();

        float sacc[8][4];
        #pragma unroll
        for (int nt = 0; nt < 8; nt++)
            #pragma unroll
            for (int j = 0; j < 4; j++) sacc[nt][j] = 0.0f;

        #pragma unroll
        for (int kt = 0; kt < 8; kt++) {
            int dcol = kt * 8 + tig;
            #pragma unroll
            for (int nt = 0; nt < 8; nt++) {
                uint32_t b0 = Ks[(nt * 8 + g) * KVS + dcol];
                uint32_t b1 = Ks[(nt * 8 + g) * KVS + dcol + 4];
                mma_tf32(sacc[nt], qf[kt], b0, b1);
            }
        }

        float mt_lo = -1e30f, mt_hi = -1e30f;
        #pragma unroll
        for (int nt = 0; nt < 8; nt++) {
            mt_lo = fmaxf(mt_lo, fmaxf(sacc[nt][0], sacc[nt][1]));
            mt_hi = fmaxf(mt_hi, fmaxf(sacc[nt][2], sacc[nt][3]));
        }
        mt_lo = fmaxf(mt_lo, __shfl_xor_sync(0xffffffffu, mt_lo, 1));
        mt_lo = fmaxf(mt_lo, __shfl_xor_sync(0xffffffffu, mt_lo, 2));
        mt_hi = fmaxf(mt_hi, __shfl_xor_sync(0xffffffffu, mt_hi, 1));
        mt_hi = fmaxf(mt_hi, __shfl_xor_sync(0xffffffffu, mt_hi, 2));

        float mn_lo = fmaxf(m_lo, mt_lo);
        float mn_hi = fmaxf(m_hi, mt_hi);
        float corr_lo = __expf(m_lo - mn_lo);
        float corr_hi = __expf(m_hi - mn_hi);
        m_lo = mn_lo;
        m_hi = mn_hi;

        float rs_lo = 0.0f, rs_hi = 0.0f;
        uint32_t pf[8][4];
        #pragma unroll
        for (int nt = 0; nt < 8; nt++) {
            float p0 = __expf(sacc[nt][0] - m_lo);
            float p1 = __expf(sacc[nt][1] - m_lo);
            float p2 = __expf(sacc[nt][2] - m_hi);
            float p3 = __expf(sacc[nt][3] - m_hi);
            rs_lo += p0 + p1;
            rs_hi += p2 + p3;
            pf[nt][0] = f2tf32(p0);
            pf[nt][1] = f2tf32(p2);
            pf[nt][2] = f2tf32(p1);
            pf[nt][3] = f2tf32(p3);
        }
        rs_lo += __shfl_xor_sync(0xffffffffu, rs_lo, 1);
        rs_lo += __shfl_xor_sync(0xffffffffu, rs_lo, 2);
        rs_hi += __shfl_xor_sync(0xffffffffu, rs_hi, 1);
        rs_hi += __shfl_xor_sync(0xffffffffu, rs_hi, 2);
        l_lo = l_lo * corr_lo + rs_lo;
        l_hi = l_hi * corr_hi + rs_hi;

        #pragma unroll
        for (int nt = 0; nt < 8; nt++) {
            oacc[nt][0] *= corr_lo;
            oacc[nt][1] *= corr_lo;
            oacc[nt][2] *= corr_hi;
            oacc[nt][3] *= corr_hi;
        }

        #pragma unroll
        for (int kt = 0; kt < 8; kt++) {
            int r0 = kt * 8 + 2 * tig;
            #pragma unroll
            for (int nt = 0; nt < 8; nt++) {
                uint32_t b0 = Vs[r0 * KVS + nt * 8 + g];
                uint32_t b1 = Vs[(r0 + 1) * KVS + nt * 8 + g];
                mma_tf32(oacc[nt], pf[kt], b0, b1);
            }
        }
    }

    float inv_lo = 1.0f / l_lo;
    float inv_hi = 1.0f / l_hi;
    float* Ob = O + ((size_t)(b * SQ_LEN + q0 + w * 16)) * D_MODEL + h * 64;
    #pragma unroll
    for (int nt = 0; nt < 8; nt++) {
        int col = nt * 8 + 2 * tig;
        float2 v0 = make_float2(oacc[nt][0] * inv_lo, oacc[nt][1] * inv_lo);
        float2 v1 = make_float2(oacc[nt][2] * inv_hi, oacc[nt][3] * inv_hi);
        *(float2*)(Ob + (size_t)g       * D_MODEL + col) = v0;
        *(float2*)(Ob + (size_t)(g + 8) * D_MODEL + col) = v1;
    }
}

// ---------------------------------------------------------------------------
extern "C" void kernel_launch(void* const* d_in, const int* in_sizes, int n_in,
                              void* d_out, int out_size) {
    const float* hs  = (const float*)d_in[0];
    const float* enc = (const float*)d_in[1];
    const float* Wq  = (const float*)d_in[2];
    const float* bq  = (const float*)d_in[3];
    const float* Wk  = (const float*)d_in[4];
    const float* bk  = (const float*)d_in[5];
    const float* Wv  = (const float*)d_in[6];
    const float* bv  = (const float*)d_in[7];
    const float* Wo  = (const float*)d_in[8];
    const float* bo  = (const float*)d_in[9];
    float* out = (float*)d_out;

    float *Qp, *Kp, *Vp, *Cp;
    cudaGetSymbolAddress((void**)&Qp, g_Q);
    cudaGetSymbolAddress((void**)&Kp, g_K);
    cudaGetSymbolAddress((void**)&Vp, g_V);
    cudaGetSymbolAddress((void**)&Cp, g_ctx);

    const int MQ  = NB * SQ_LEN;    // 4096
    const int MKV = NB * SKV_LEN;   // 8192

    gemm3xtf32_bias<<<dim3(MQ / 128, 12), 128>>>(hs, Wq, bq, Qp);
    gemm3xtf32_bias<<<dim3(MKV / 128, 12), 128>>>(enc, Wk, bk, Kp);
    gemm3xtf32_bias<<<dim3(MKV / 128, 12), 128>>>(enc, Wv, bv, Vp);

    attention_mma<<<dim3(SQ_LEN / 64, NH, NB), 128>>>(Qp, Kp, Vp, Cp);

    gemm3xtf32_bias<<<dim3(MQ / 128, 12), 128>>>(Cp, Wo, bo, out);
}